// round 8
// baseline (speedup 1.0000x reference)
#include <cuda_runtime.h>
#include <cuda_bf16.h>
#include <math_constants.h>
#include <cstdint>

#define NN   10000
#define FF   128
#define DEG  32
#define OUTF 128

// ---------------------------------------------------------------------------
// Scratch (__device__ globals; no allocation allowed)
// ---------------------------------------------------------------------------
__device__ float         g_C[(size_t)NN * 512];     // 0.5 * center projections, fp32
__device__ __nv_bfloat16 g_P[(size_t)NN * 512];     // 0.5 * neighbor projections, bf16
__device__ __nv_bfloat16 g_Xb[(size_t)NN * 128];    // X in bf16
__device__ __nv_bfloat16 g_Wb[(size_t)1024 * 128];  // Wbig transposed (for gemm_cp)
__device__ __nv_bfloat16 g_A2[(size_t)NN * 1536];   // H split: [2k]=hi,[2k+1]=lo (k<512); [1024+k]=hi
__device__ __nv_bfloat16 g_B2[(size_t)128 * 1536];  // W split: [2k]=[2k+1]=Whi; [1024+k]=Wlo

// ---------------------------------------------------------------------------
// Helpers
// ---------------------------------------------------------------------------
__device__ __forceinline__ uint32_t smem_u32(const void* p) {
    uint32_t a;
    asm("{ .reg .u64 t; cvta.to.shared.u64 t, %1; cvt.u32.u64 %0, t; }" : "=r"(a) : "l"(p));
    return a;
}
__device__ __forceinline__ void ldmatrix_x4(uint32_t* r, uint32_t addr) {
    asm volatile("ldmatrix.sync.aligned.m8n8.x4.shared.b16 {%0,%1,%2,%3}, [%4];"
                 : "=r"(r[0]), "=r"(r[1]), "=r"(r[2]), "=r"(r[3]) : "r"(addr));
}
__device__ __forceinline__ void ldmatrix_x2(uint32_t* r, uint32_t addr) {
    asm volatile("ldmatrix.sync.aligned.m8n8.x2.shared.b16 {%0,%1}, [%2];"
                 : "=r"(r[0]), "=r"(r[1]) : "r"(addr));
}
__device__ __forceinline__ void mma_bf16(float* c, const uint32_t* a, const uint32_t* b) {
    asm volatile(
        "mma.sync.aligned.m16n8k16.row.col.f32.bf16.bf16.f32 "
        "{%0,%1,%2,%3}, {%4,%5,%6,%7}, {%8,%9}, {%0,%1,%2,%3};"
        : "+f"(c[0]), "+f"(c[1]), "+f"(c[2]), "+f"(c[3])
        : "r"(a[0]), "r"(a[1]), "r"(a[2]), "r"(a[3]), "r"(b[0]), "r"(b[1]));
}
__device__ __forceinline__ void cp_async16(uint32_t smaddr, const void* gptr) {
    asm volatile("cp.async.ca.shared.global [%0], [%1], 16;"
                 :: "r"(smaddr), "l"(gptr) : "memory");
}
__device__ __forceinline__ uint32_t pack_bf2(__nv_bfloat16 a, __nv_bfloat16 b) {
    __nv_bfloat162 h; h.x = a; h.y = b;
    return *reinterpret_cast<uint32_t*>(&h);
}
__device__ __forceinline__ void bsplit(float v, __nv_bfloat16& hi, __nv_bfloat16& lo) {
    hi = __float2bfloat16_rn(v);
    lo = __float2bfloat16_rn(v - __bfloat162float(hi));
}

// ===========================================================================
// Kernel 0: prep — X->bf16; Wb (transposed Wbig, bf16); B2 (split W for out-GEMM)
// ===========================================================================
__global__ __launch_bounds__(256) void prep_kernel(
    const float* __restrict__ X,
    const float* __restrict__ Wsum, const float* __restrict__ Wmean,
    const float* __restrict__ Wmax, const float* __restrict__ Wmin,
    const float* __restrict__ W)
{
    const int tid = blockIdx.x * blockDim.x + threadIdx.x;
    const int stride = gridDim.x * blockDim.x;

    const float4* X4 = (const float4*)X;
    for (int v = tid; v < NN * 128 / 4; v += stride) {
        float4 f = X4[v];
        uint2 pk;
        pk.x = pack_bf2(__float2bfloat16_rn(f.x), __float2bfloat16_rn(f.y));
        pk.y = pack_bf2(__float2bfloat16_rn(f.z), __float2bfloat16_rn(f.w));
        *(uint2*)&g_Xb[(size_t)v * 4] = pk;
    }

    for (int v = tid; v < 1024 * 32; v += stride) {
        int n  = v >> 5;
        int k4 = (v & 31) * 4;
        int m  = (n >> 7) & 3;
        const float* __restrict__ Wm = (m == 0) ? Wsum : (m == 1) ? Wmean : (m == 2) ? Wmax : Wmin;
        int rowOff = (n >= 512) ? 128 : 0;
        int f = n & 127;
        float a0 = Wm[(rowOff + k4 + 0) * 128 + f];
        float a1 = Wm[(rowOff + k4 + 1) * 128 + f];
        float a2 = Wm[(rowOff + k4 + 2) * 128 + f];
        float a3 = Wm[(rowOff + k4 + 3) * 128 + f];
        uint2 pk;
        pk.x = pack_bf2(__float2bfloat16_rn(a0), __float2bfloat16_rn(a1));
        pk.y = pack_bf2(__float2bfloat16_rn(a2), __float2bfloat16_rn(a3));
        *(uint2*)&g_Wb[(size_t)n * 128 + k4] = pk;
    }

    // B2: [n][1536]: [2k]=[2k+1]=hi(W[k][n]); [1024+k]=lo
    for (int v = tid; v < 128 * 512; v += stride) {
        int n = v & 127;
        int k = v >> 7;
        float w = W[(size_t)k * 128 + n];
        __nv_bfloat16 hi, lo;
        bsplit(w, hi, lo);
        g_B2[(size_t)n * 1536 + 2 * k]     = hi;
        g_B2[(size_t)n * 1536 + 2 * k + 1] = hi;
        g_B2[(size_t)n * 1536 + 1024 + k]  = lo;
    }
}

// ===========================================================================
// Kernel 1: CP = 0.5 * (Xb @ Wb^T) via bf16 mma (M=10000, N=1024, K=128)
// CTA tile 128x128; 8 warps (4m x 2n), warp tile 32x64.
// Loads split into two commit groups (K-halves) so compute on half 0
// overlaps the in-flight half 1.
// ===========================================================================
#define CP_STRIDE 136

__global__ __launch_bounds__(256) void gemm_cp_mma_kernel()
{
    extern __shared__ char smem[];
    __nv_bfloat16* Xs = (__nv_bfloat16*)smem;
    __nv_bfloat16* Ws = (__nv_bfloat16*)(smem + 128 * CP_STRIDE * 2);

    const int tid  = threadIdx.x;
    const int lane = tid & 31;
    const int wid  = tid >> 5;
    const int warpM = wid >> 1;
    const int warpN = wid & 1;

    const int nBase   = blockIdx.x * 128;
    const int rowBase = blockIdx.y * 128;

    const uint32_t sXsB = smem_u32(Xs);
    const uint32_t sWsB = smem_u32(Ws);

    // Group 0: K columns 0..63 (quads 0..7) of A and B
#pragma unroll
    for (int h = 0; h < 2; h++) {
        for (int v = tid; v < 1024; v += 256) {
            int r = v >> 3, q = (v & 7) + h * 8;
            int grow = rowBase + r;
            if (grow >= NN) grow = 0;   // rows >= NN discarded in epilogue
            cp_async16(sXsB + (r * CP_STRIDE + q * 8) * 2,
                       &g_Xb[(size_t)grow * 128 + q * 8]);
        }
        for (int v = tid; v < 1024; v += 256) {
            int n = v >> 3, q = (v & 7) + h * 8;
            cp_async16(sWsB + (n * CP_STRIDE + q * 8) * 2,
                       &g_Wb[(size_t)(nBase + n) * 128 + q * 8]);
        }
        asm volatile("cp.async.commit_group;" ::: "memory");
    }

    float acc[2][8][4];
#pragma unroll
    for (int mt = 0; mt < 2; mt++)
#pragma unroll
        for (int nt = 0; nt < 8; nt++)
#pragma unroll
            for (int e = 0; e < 4; e++) acc[mt][nt][e] = 0.f;

    asm volatile("cp.async.wait_group 1;" ::: "memory");  // half 0 ready
    __syncthreads();

#pragma unroll
    for (int half = 0; half < 2; half++) {
        if (half == 1) {
            asm volatile("cp.async.wait_group 0;" ::: "memory");
            __syncthreads();
        }
#pragma unroll
        for (int kk = 0; kk < 64; kk += 16) {
            const int kb = half * 64 + kk;
            uint32_t aF[2][4];
#pragma unroll
            for (int mt = 0; mt < 2; mt++) {
                int row = warpM * 32 + mt * 16 + (lane & 15);
                int col = kb + (lane >> 4) * 8;
                ldmatrix_x4(aF[mt], sXsB + (row * CP_STRIDE + col) * 2);
            }
            uint32_t bF[8][2];
#pragma unroll
            for (int nt = 0; nt < 8; nt++) {
                int nrow = warpN * 64 + nt * 8 + (lane & 7);
                int col  = kb + ((lane & 15) >> 3) * 8;
                ldmatrix_x2(bF[nt], sWsB + (nrow * CP_STRIDE + col) * 2);
            }
#pragma unroll
            for (int mt = 0; mt < 2; mt++)
#pragma unroll
                for (int nt = 0; nt < 8; nt++)
                    mma_bf16(acc[mt][nt], aF[mt], bF[nt]);
        }
    }

    // Epilogue: store 0.5*value (folds sigmoid's a/2 into the projections)
#pragma unroll
    for (int mt = 0; mt < 2; mt++) {
        const int r0 = rowBase + warpM * 32 + mt * 16 + (lane >> 2);
        const int r1 = r0 + 8;
#pragma unroll
        for (int nt = 0; nt < 8; nt++) {
            const int cLoc = warpN * 64 + nt * 8 + (lane & 3) * 2;
            const int cAbs = nBase + cLoc;
            float v00 = 0.5f * acc[mt][nt][0], v01 = 0.5f * acc[mt][nt][1];
            float v10 = 0.5f * acc[mt][nt][2], v11 = 0.5f * acc[mt][nt][3];
            if (cAbs < 512) {
                if (r0 < NN) *(float2*)&g_C[(size_t)r0 * 512 + cAbs] = make_float2(v00, v01);
                if (r1 < NN) *(float2*)&g_C[(size_t)r1 * 512 + cAbs] = make_float2(v10, v11);
            } else {
                const int cP = cAbs - 512;
                if (r0 < NN)
                    *(uint32_t*)&g_P[(size_t)r0 * 512 + cP] =
                        pack_bf2(__float2bfloat16_rn(v00), __float2bfloat16_rn(v01));
                if (r1 < NN)
                    *(uint32_t*)&g_P[(size_t)r1 * 512 + cP] =
                        pack_bf2(__float2bfloat16_rn(v10), __float2bfloat16_rn(v11));
            }
        }
    }
}

// ===========================================================================
// Kernel 2: per-node aggregation -> A2 (bf16 hi/lo split of H)
// ===========================================================================
__device__ __forceinline__ float tanha(float a) {
    float t;
    asm("tanh.approx.f32 %0, %1;" : "=f"(t) : "f"(a));
    return t;
}
__device__ __forceinline__ float4 add4(float4 a, float4 b) {
    return make_float4(a.x + b.x, a.y + b.y, a.z + b.z, a.w + b.w);
}
__device__ __forceinline__ float4 max4(float4 a, float4 b) {
    return make_float4(fmaxf(a.x, b.x), fmaxf(a.y, b.y), fmaxf(a.z, b.z), fmaxf(a.w, b.w));
}
__device__ __forceinline__ float4 min4(float4 a, float4 b) {
    return make_float4(fminf(a.x, b.x), fminf(a.y, b.y), fminf(a.z, b.z), fminf(a.w, b.w));
}
__device__ __forceinline__ float4 loadP4(const __nv_bfloat16* __restrict__ p) {
    uint2 pk = *(const uint2*)p;
    __nv_bfloat162 h0 = *reinterpret_cast<__nv_bfloat162*>(&pk.x);
    __nv_bfloat162 h1 = *reinterpret_cast<__nv_bfloat162*>(&pk.y);
    float2 f0 = __bfloat1622float2(h0);
    float2 f1 = __bfloat1622float2(h1);
    return make_float4(f0.x, f0.y, f1.x, f1.y);
}
__device__ __forceinline__ float4 sigmul4(float4 c, float4 p, float4 hx) {
    return make_float4(fmaf(tanha(c.x + p.x), hx.x, hx.x),
                       fmaf(tanha(c.y + p.y), hx.y, hx.y),
                       fmaf(tanha(c.z + p.z), hx.z, hx.z),
                       fmaf(tanha(c.w + p.w), hx.w, hx.w));
}
__device__ __forceinline__ void store_split_group(
    __nv_bfloat16* a2, int koff, float4 v)
{
    __nv_bfloat16 h0, l0, h1, l1, h2, l2, h3, l3;
    bsplit(v.x, h0, l0); bsplit(v.y, h1, l1);
    bsplit(v.z, h2, l2); bsplit(v.w, h3, l3);
    uint4 pk;
    pk.x = pack_bf2(h0, l0); pk.y = pack_bf2(h1, l1);
    pk.z = pack_bf2(h2, l2); pk.w = pack_bf2(h3, l3);
    *(uint4*)&a2[2 * koff] = pk;
    uint2 t;
    t.x = pack_bf2(h0, h1); t.y = pack_bf2(h2, h3);
    *(uint2*)&a2[1024 + koff] = t;
}

__global__ __launch_bounds__(128) void agg_kernel(
    const float* __restrict__ x, const int* __restrict__ nbr)
{
    const int warp = threadIdx.x >> 5;
    const int lane = threadIdx.x & 31;
    const int i = blockIdx.x * 4 + warp;
    if (i >= NN) return;

    const int jl = nbr[i * DEG + lane];

    const float4* __restrict__ x4 = (const float4*)x;
    const float4* __restrict__ C4 = (const float4*)g_C;

    const float4 xi = x4[i * 32 + lane];
    const size_t cb = (size_t)i * 128;
    const float4 c0 = C4[cb + 0  + lane];
    const float4 c1 = C4[cb + 32 + lane];
    const float4 c2 = C4[cb + 64 + lane];
    const float4 c3 = C4[cb + 96 + lane];

    float4 s0 = make_float4(0.f, 0.f, 0.f, 0.f);
    float4 s1 = make_float4(0.f, 0.f, 0.f, 0.f);
    float4 s2 = make_float4(-CUDART_INF_F, -CUDART_INF_F, -CUDART_INF_F, -CUDART_INF_F);
    float4 s3 = make_float4( CUDART_INF_F,  CUDART_INF_F,  CUDART_INF_F,  CUDART_INF_F);

#pragma unroll 4
    for (int d = 0; d < DEG; d++) {
        const int j = __shfl_sync(0xffffffffu, jl, d);
        const float4 xj = x4[j * 32 + lane];
        const float4 hx = make_float4(0.5f * xj.x, 0.5f * xj.y, 0.5f * xj.z, 0.5f * xj.w);
        const __nv_bfloat16* __restrict__ prow = &g_P[(size_t)j * 512 + lane * 4];
        const float4 p0 = loadP4(prow + 0);
        const float4 p1 = loadP4(prow + 128);
        const float4 p2 = loadP4(prow + 256);
        const float4 p3 = loadP4(prow + 384);

        s0 = add4(s0, sigmul4(c0, p0, hx));
        s1 = add4(s1, sigmul4(c1, p1, hx));
        s2 = max4(s2, sigmul4(c2, p2, hx));
        s3 = min4(s3, sigmul4(c3, p3, hx));
    }

    const float inv_deg = 1.0f / (float)DEG;
    float4 h0 = add4(xi, s0);
    float4 h1 = add4(xi, make_float4(s1.x * inv_deg, s1.y * inv_deg,
                                     s1.z * inv_deg, s1.w * inv_deg));
    float4 h2 = add4(xi, s2);
    float4 h3 = add4(xi, s3);

    __nv_bfloat16* a2 = &g_A2[(size_t)i * 1536];
    store_split_group(a2, 0   + lane * 4, h0);
    store_split_group(a2, 128 + lane * 4, h1);
    store_split_group(a2, 256 + lane * 4, h2);
    store_split_group(a2, 384 + lane * 4, h3);
}

// ===========================================================================
// Kernel 3: out = relu(A2 @ B2^T + bias)  (M=10000, N=128, K=1536, bf16 HMMA)
// Tile M=80 x N=64 -> grid (125, 2) = 250 CTAs, 2 CTAs/SM.
// 128 threads (4 warps); warp tile 80x16. 3-stage cp.async pipeline, BK=64.
// ===========================================================================
#define OUT_NKB    24                       // 1536 / 64
#define OUT_AST    72                       // smem row stride (bf16 elems), 144B
#define OUT_ABYTES (80 * OUT_AST * 2)       // 11520
#define OUT_BBYTES (64 * OUT_AST * 2)       // 9216
#define OUT_STAGE  (OUT_ABYTES + OUT_BBYTES) // 20736
#define OUT_SMEM   (3 * OUT_STAGE)          // 62208

__global__ __launch_bounds__(128) void gemm_out_bsplit_kernel(
    const float* __restrict__ bias, float* __restrict__ out)
{
    extern __shared__ char smem[];
    const uint32_t sbase = smem_u32(smem);
    const int tid  = threadIdx.x;
    const int lane = tid & 31;
    const int wid  = tid >> 5;
    const int rowBase   = blockIdx.x * 80;
    const int nTileBase = blockIdx.y * 64;
    const int nbase     = wid * 16;          // local within the 64-wide tile

    float acc[5][2][4];
#pragma unroll
    for (int mt = 0; mt < 5; mt++)
#pragma unroll
        for (int nt = 0; nt < 2; nt++)
#pragma unroll
            for (int e = 0; e < 4; e++) acc[mt][nt][e] = 0.f;

    // ---- async load of one BK=64 chunk (8 quads per row) into stage s ----
    auto issue = [&](int kb, int s) {
        const uint32_t abase = sbase + s * OUT_STAGE;
        for (int v = tid; v < 640; v += 128) {          // A: 80 rows x 8 quads
            int r = v >> 3, q = v & 7;
            cp_async16(abase + (r * OUT_AST + q * 8) * 2,
                       &g_A2[(size_t)(rowBase + r) * 1536 + kb * 64 + q * 8]);
        }
        const uint32_t bbase = abase + OUT_ABYTES;
        for (int v = tid; v < 512; v += 128) {          // B: 64 rows x 8 quads
            int n = v >> 3, q = v & 7;
            cp_async16(bbase + (n * OUT_AST + q * 8) * 2,
                       &g_B2[(size_t)(nTileBase + n) * 1536 + kb * 64 + q * 8]);
        }
        asm volatile("cp.async.commit_group;" ::: "memory");
    };

    issue(0, 0);
    issue(1, 1);
    issue(2, 2);

    for (int kb = 0; kb < OUT_NKB; kb++) {
        // Wait until chunk kb is complete. Pending groups after this wait:
        // min(OUT_NKB, kb+3) - (kb+1).
        if (kb < OUT_NKB - 2)
            asm volatile("cp.async.wait_group 2;" ::: "memory");
        else if (kb == OUT_NKB - 2)
            asm volatile("cp.async.wait_group 1;" ::: "memory");
        else
            asm volatile("cp.async.wait_group 0;" ::: "memory");
        __syncthreads();

        const int s = kb % 3;
        const uint32_t aS = sbase + s * OUT_STAGE;
        const uint32_t bS = aS + OUT_ABYTES;

#pragma unroll
        for (int ks = 0; ks < 4; ks++) {
            const int col = ks * 16;
            uint32_t aF[5][4];
#pragma unroll
            for (int mt = 0; mt < 5; mt++) {
                int row = mt * 16 + (lane & 15);
                ldmatrix_x4(aF[mt], aS + (row * OUT_AST + col + (lane >> 4) * 8) * 2);
            }
            uint32_t bF[2][2];
#pragma unroll
            for (int nt = 0; nt < 2; nt++) {
                int nrow = nbase + nt * 8 + (lane & 7);
                ldmatrix_x2(bF[nt], bS + (nrow * OUT_AST + col + ((lane & 15) >> 3) * 8) * 2);
            }
#pragma unroll
            for (int mt = 0; mt < 5; mt++)
#pragma unroll
                for (int nt = 0; nt < 2; nt++)
                    mma_bf16(acc[mt][nt], aF[mt], bF[nt]);
        }
        __syncthreads();

        if (kb + 3 < OUT_NKB) issue(kb + 3, s);
    }

    // Epilogue: bias + relu
#pragma unroll
    for (int mt = 0; mt < 5; mt++) {
        const int r0 = rowBase + mt * 16 + (lane >> 2);
        const int r1 = r0 + 8;
#pragma unroll
        for (int nt = 0; nt < 2; nt++) {
            const int c = nTileBase + nbase + nt * 8 + (lane & 3) * 2;
            const float b0 = bias[c], b1 = bias[c + 1];
            *(float2*)&out[(size_t)r0 * 128 + c] = make_float2(
                fmaxf(acc[mt][nt][0] + b0, 0.f), fmaxf(acc[mt][nt][1] + b1, 0.f));
            *(float2*)&out[(size_t)r1 * 128 + c] = make_float2(
                fmaxf(acc[mt][nt][2] + b0, 0.f), fmaxf(acc[mt][nt][3] + b1, 0.f));
        }
    }
}

// ===========================================================================
extern "C" void kernel_launch(void* const* d_in, const int* in_sizes, int n_in,
                              void* d_out, int out_size)
{
    const float* x     = (const float*)d_in[0];
    const int*   nbr   = (const int*)  d_in[1];
    const float* Wsum  = (const float*)d_in[2];
    const float* Wmean = (const float*)d_in[3];
    const float* Wmax  = (const float*)d_in[4];
    const float* Wmin  = (const float*)d_in[5];
    const float* W     = (const float*)d_in[6];
    const float* bias  = (const float*)d_in[7];
    float* out = (float*)d_out;

    const int CP_SMEM = 2 * 128 * CP_STRIDE * 2;  // 69,632 B
    cudaFuncSetAttribute(gemm_cp_mma_kernel,
                         cudaFuncAttributeMaxDynamicSharedMemorySize, CP_SMEM);
    cudaFuncSetAttribute(gemm_out_bsplit_kernel,
                         cudaFuncAttributeMaxDynamicSharedMemorySize, OUT_SMEM);

    // 0) conversions + weight splits
    prep_kernel<<<296, 256>>>(x, Wsum, Wmean, Wmax, Wmin, W);

    // 1) CP = 0.5 * Xb @ Wb^T (10000 x 1024), bf16 HMMA
    {
        dim3 grid(1024 / 128, (NN + 127) / 128);
        gemm_cp_mma_kernel<<<grid, 256, CP_SMEM>>>();
    }

    // 2) per-node aggregation -> A2 (split H)
    {
        dim3 grid((NN + 3) / 4);
        agg_kernel<<<grid, 128>>>(x, nbr);
    }

    // 3) out = relu(A2 @ B2^T + bias), bf16 HMMA split-precision, 3-stage pipe
    {
        dim3 grid(125, 2);
        gemm_out_bsplit_kernel<<<grid, 128, OUT_SMEM>>>(bias, out);
    }
}

// round 9
// speedup vs baseline: 1.0792x; 1.0792x over previous
#include <cuda_runtime.h>
#include <cuda_bf16.h>
#include <cuda_fp16.h>
#include <math_constants.h>
#include <cstdint>

#define NN   10000
#define FF   128
#define DEG  32
#define OUTF 128

// ---------------------------------------------------------------------------
// Scratch (__device__ globals; no allocation allowed)
// ---------------------------------------------------------------------------
__device__ __half        g_Ch[(size_t)NN * 512];    // 0.5 * center projections, fp16
__device__ __half        g_P[(size_t)NN * 512];     // 0.5 * neighbor projections, fp16
__device__ __half        g_Xh[(size_t)NN * 128];    // 0.5 * X in fp16 (agg)
__device__ __nv_bfloat16 g_Xb[(size_t)NN * 128];    // X in bf16 (gemm_cp)
__device__ __nv_bfloat16 g_Wb[(size_t)1024 * 128];  // Wbig transposed (gemm_cp)
__device__ __nv_bfloat16 g_A2[(size_t)NN * 1536];   // H split: [2k]=hi,[2k+1]=lo; [1024+k]=hi
__device__ __nv_bfloat16 g_B2[(size_t)128 * 1536];  // W split: [2k]=[2k+1]=Whi; [1024+k]=Wlo

// ---------------------------------------------------------------------------
// Helpers
// ---------------------------------------------------------------------------
__device__ __forceinline__ uint32_t smem_u32(const void* p) {
    uint32_t a;
    asm("{ .reg .u64 t; cvta.to.shared.u64 t, %1; cvt.u32.u64 %0, t; }" : "=r"(a) : "l"(p));
    return a;
}
__device__ __forceinline__ void ldmatrix_x4(uint32_t* r, uint32_t addr) {
    asm volatile("ldmatrix.sync.aligned.m8n8.x4.shared.b16 {%0,%1,%2,%3}, [%4];"
                 : "=r"(r[0]), "=r"(r[1]), "=r"(r[2]), "=r"(r[3]) : "r"(addr));
}
__device__ __forceinline__ void ldmatrix_x2(uint32_t* r, uint32_t addr) {
    asm volatile("ldmatrix.sync.aligned.m8n8.x2.shared.b16 {%0,%1}, [%2];"
                 : "=r"(r[0]), "=r"(r[1]) : "r"(addr));
}
__device__ __forceinline__ void mma_bf16(float* c, const uint32_t* a, const uint32_t* b) {
    asm volatile(
        "mma.sync.aligned.m16n8k16.row.col.f32.bf16.bf16.f32 "
        "{%0,%1,%2,%3}, {%4,%5,%6,%7}, {%8,%9}, {%0,%1,%2,%3};"
        : "+f"(c[0]), "+f"(c[1]), "+f"(c[2]), "+f"(c[3])
        : "r"(a[0]), "r"(a[1]), "r"(a[2]), "r"(a[3]), "r"(b[0]), "r"(b[1]));
}
__device__ __forceinline__ void cp_async16(uint32_t smaddr, const void* gptr) {
    asm volatile("cp.async.ca.shared.global [%0], [%1], 16;"
                 :: "r"(smaddr), "l"(gptr) : "memory");
}
__device__ __forceinline__ uint32_t pack_bf2(__nv_bfloat16 a, __nv_bfloat16 b) {
    __nv_bfloat162 h; h.x = a; h.y = b;
    return *reinterpret_cast<uint32_t*>(&h);
}
__device__ __forceinline__ void bsplit(float v, __nv_bfloat16& hi, __nv_bfloat16& lo) {
    hi = __float2bfloat16_rn(v);
    lo = __float2bfloat16_rn(v - __bfloat162float(hi));
}
__device__ __forceinline__ __half2 htanh2(__half2 a) {
    uint32_t av = *reinterpret_cast<uint32_t*>(&a), rv;
    asm("tanh.approx.f16x2 %0, %1;" : "=r"(rv) : "r"(av));
    return *reinterpret_cast<__half2*>(&rv);
}

// ===========================================================================
// Kernel 0: prep — Xb bf16; Xh fp16(0.5x); Wb transposed bf16; B2 split W
// ===========================================================================
__global__ __launch_bounds__(256) void prep_kernel(
    const float* __restrict__ X,
    const float* __restrict__ Wsum, const float* __restrict__ Wmean,
    const float* __restrict__ Wmax, const float* __restrict__ Wmin,
    const float* __restrict__ W)
{
    const int tid = blockIdx.x * blockDim.x + threadIdx.x;
    const int stride = gridDim.x * blockDim.x;

    const float4* X4 = (const float4*)X;
    for (int v = tid; v < NN * 128 / 4; v += stride) {
        float4 f = X4[v];
        uint2 pk;
        pk.x = pack_bf2(__float2bfloat16_rn(f.x), __float2bfloat16_rn(f.y));
        pk.y = pack_bf2(__float2bfloat16_rn(f.z), __float2bfloat16_rn(f.w));
        *(uint2*)&g_Xb[(size_t)v * 4] = pk;
        __half2 h0 = __floats2half2_rn(0.5f * f.x, 0.5f * f.y);
        __half2 h1 = __floats2half2_rn(0.5f * f.z, 0.5f * f.w);
        uint2 ph;
        ph.x = *reinterpret_cast<uint32_t*>(&h0);
        ph.y = *reinterpret_cast<uint32_t*>(&h1);
        *(uint2*)&g_Xh[(size_t)v * 4] = ph;
    }

    for (int v = tid; v < 1024 * 32; v += stride) {
        int n  = v >> 5;
        int k4 = (v & 31) * 4;
        int m  = (n >> 7) & 3;
        const float* __restrict__ Wm = (m == 0) ? Wsum : (m == 1) ? Wmean : (m == 2) ? Wmax : Wmin;
        int rowOff = (n >= 512) ? 128 : 0;
        int f = n & 127;
        float a0 = Wm[(rowOff + k4 + 0) * 128 + f];
        float a1 = Wm[(rowOff + k4 + 1) * 128 + f];
        float a2 = Wm[(rowOff + k4 + 2) * 128 + f];
        float a3 = Wm[(rowOff + k4 + 3) * 128 + f];
        uint2 pk;
        pk.x = pack_bf2(__float2bfloat16_rn(a0), __float2bfloat16_rn(a1));
        pk.y = pack_bf2(__float2bfloat16_rn(a2), __float2bfloat16_rn(a3));
        *(uint2*)&g_Wb[(size_t)n * 128 + k4] = pk;
    }

    // B2: [n][1536]: [2k]=[2k+1]=hi(W[k][n]); [1024+k]=lo
    for (int v = tid; v < 128 * 512; v += stride) {
        int n = v & 127;
        int k = v >> 7;
        float w = W[(size_t)k * 128 + n];
        __nv_bfloat16 hi, lo;
        bsplit(w, hi, lo);
        g_B2[(size_t)n * 1536 + 2 * k]     = hi;
        g_B2[(size_t)n * 1536 + 2 * k + 1] = hi;
        g_B2[(size_t)n * 1536 + 1024 + k]  = lo;
    }
}

// ===========================================================================
// Kernel 1: CP = 0.5 * (Xb @ Wb^T) via bf16 mma (M=10000, N=1024, K=128)
// CTA tile 128x128; 8 warps (4m x 2n), warp tile 32x64. Two commit groups.
// Epilogue stores fp16 (g_Ch for cols<512, g_P for cols>=512).
// ===========================================================================
#define CP_STRIDE 136

__global__ __launch_bounds__(256) void gemm_cp_mma_kernel()
{
    extern __shared__ char smem[];
    __nv_bfloat16* Xs = (__nv_bfloat16*)smem;
    __nv_bfloat16* Ws = (__nv_bfloat16*)(smem + 128 * CP_STRIDE * 2);

    const int tid  = threadIdx.x;
    const int lane = tid & 31;
    const int wid  = tid >> 5;
    const int warpM = wid >> 1;
    const int warpN = wid & 1;

    const int nBase   = blockIdx.x * 128;
    const int rowBase = blockIdx.y * 128;

    const uint32_t sXsB = smem_u32(Xs);
    const uint32_t sWsB = smem_u32(Ws);

#pragma unroll
    for (int h = 0; h < 2; h++) {
        for (int v = tid; v < 1024; v += 256) {
            int r = v >> 3, q = (v & 7) + h * 8;
            int grow = rowBase + r;
            if (grow >= NN) grow = 0;   // rows >= NN discarded in epilogue
            cp_async16(sXsB + (r * CP_STRIDE + q * 8) * 2,
                       &g_Xb[(size_t)grow * 128 + q * 8]);
        }
        for (int v = tid; v < 1024; v += 256) {
            int n = v >> 3, q = (v & 7) + h * 8;
            cp_async16(sWsB + (n * CP_STRIDE + q * 8) * 2,
                       &g_Wb[(size_t)(nBase + n) * 128 + q * 8]);
        }
        asm volatile("cp.async.commit_group;" ::: "memory");
    }

    float acc[2][8][4];
#pragma unroll
    for (int mt = 0; mt < 2; mt++)
#pragma unroll
        for (int nt = 0; nt < 8; nt++)
#pragma unroll
            for (int e = 0; e < 4; e++) acc[mt][nt][e] = 0.f;

    asm volatile("cp.async.wait_group 1;" ::: "memory");
    __syncthreads();

#pragma unroll
    for (int half = 0; half < 2; half++) {
        if (half == 1) {
            asm volatile("cp.async.wait_group 0;" ::: "memory");
            __syncthreads();
        }
#pragma unroll
        for (int kk = 0; kk < 64; kk += 16) {
            const int kb = half * 64 + kk;
            uint32_t aF[2][4];
#pragma unroll
            for (int mt = 0; mt < 2; mt++) {
                int row = warpM * 32 + mt * 16 + (lane & 15);
                int col = kb + (lane >> 4) * 8;
                ldmatrix_x4(aF[mt], sXsB + (row * CP_STRIDE + col) * 2);
            }
            uint32_t bF[8][2];
#pragma unroll
            for (int nt = 0; nt < 8; nt++) {
                int nrow = warpN * 64 + nt * 8 + (lane & 7);
                int col  = kb + ((lane & 15) >> 3) * 8;
                ldmatrix_x2(bF[nt], sWsB + (nrow * CP_STRIDE + col) * 2);
            }
#pragma unroll
            for (int mt = 0; mt < 2; mt++)
#pragma unroll
                for (int nt = 0; nt < 8; nt++)
                    mma_bf16(acc[mt][nt], aF[mt], bF[nt]);
        }
    }

    // Epilogue: store 0.5*value in fp16 (C half and P half identical form)
#pragma unroll
    for (int mt = 0; mt < 2; mt++) {
        const int r0 = rowBase + warpM * 32 + mt * 16 + (lane >> 2);
        const int r1 = r0 + 8;
#pragma unroll
        for (int nt = 0; nt < 8; nt++) {
            const int cLoc = warpN * 64 + nt * 8 + (lane & 3) * 2;
            const int cAbs = nBase + cLoc;
            __half* dstBase = (cAbs < 512) ? g_Ch : g_P;
            const int cOut = cAbs & 511;
            if (r0 < NN) {
                __half2 h = __floats2half2_rn(0.5f * acc[mt][nt][0], 0.5f * acc[mt][nt][1]);
                *(uint32_t*)&dstBase[(size_t)r0 * 512 + cOut] = *reinterpret_cast<uint32_t*>(&h);
            }
            if (r1 < NN) {
                __half2 h = __floats2half2_rn(0.5f * acc[mt][nt][2], 0.5f * acc[mt][nt][3]);
                *(uint32_t*)&dstBase[(size_t)r1 * 512 + cOut] = *reinterpret_cast<uint32_t*>(&h);
            }
        }
    }
}

// ===========================================================================
// Kernel 2: per-node aggregation (half2 pipeline) -> A2 (bf16 hi/lo split of H)
// mask*x = fma(tanh.f16x2(c+p), hx, hx); c,p,hx all pre-halved fp16.
// ===========================================================================
__device__ __forceinline__ float4 add4(float4 a, float4 b) {
    return make_float4(a.x + b.x, a.y + b.y, a.z + b.z, a.w + b.w);
}
__device__ __forceinline__ void bsplit_store(__nv_bfloat16* a2, int koff, float4 v) {
    __nv_bfloat16 h0, l0, h1, l1, h2, l2, h3, l3;
    bsplit(v.x, h0, l0); bsplit(v.y, h1, l1);
    bsplit(v.z, h2, l2); bsplit(v.w, h3, l3);
    uint4 pk;
    pk.x = pack_bf2(h0, l0); pk.y = pack_bf2(h1, l1);
    pk.z = pack_bf2(h2, l2); pk.w = pack_bf2(h3, l3);
    *(uint4*)&a2[2 * koff] = pk;
    uint2 t;
    t.x = pack_bf2(h0, h1); t.y = pack_bf2(h2, h3);
    *(uint2*)&a2[1024 + koff] = t;
}
__device__ __forceinline__ void ld_h2pair(const __half* p, __half2& a, __half2& b) {
    uint2 v = *(const uint2*)p;
    a = *reinterpret_cast<__half2*>(&v.x);
    b = *reinterpret_cast<__half2*>(&v.y);
}

__global__ __launch_bounds__(128) void agg_kernel(
    const float* __restrict__ x, const int* __restrict__ nbr)
{
    const int warp = threadIdx.x >> 5;
    const int lane = threadIdx.x & 31;
    const int i = blockIdx.x * 4 + warp;
    if (i >= NN) return;

    const int jl = nbr[i * DEG + lane];
    const float4* __restrict__ x4 = (const float4*)x;

    const float4 xi = x4[i * 32 + lane];

    // center projections (fp16, pre-halved): 4 masks x 2 half2
    __half2 c0a, c0b, c1a, c1b, c2a, c2b, c3a, c3b;
    {
        const __half* crow = &g_Ch[(size_t)i * 512 + lane * 4];
        ld_h2pair(crow + 0,   c0a, c0b);
        ld_h2pair(crow + 128, c1a, c1b);
        ld_h2pair(crow + 256, c2a, c2b);
        ld_h2pair(crow + 384, c3a, c3b);
    }

    float4 s0 = make_float4(0.f, 0.f, 0.f, 0.f);
    float4 s1 = make_float4(0.f, 0.f, 0.f, 0.f);
    const uint32_t NINF2 = 0xFC00FC00u, PINF2 = 0x7C007C00u;
    __half2 s2a = *reinterpret_cast<const __half2*>(&NINF2);
    __half2 s2b = s2a;
    __half2 s3a = *reinterpret_cast<const __half2*>(&PINF2);
    __half2 s3b = s3a;

#pragma unroll 4
    for (int d = 0; d < DEG; d++) {
        const int j = __shfl_sync(0xffffffffu, jl, d);

        __half2 hxa, hxb;   // 0.5*x_j (fp16)
        ld_h2pair(&g_Xh[(size_t)j * 128 + lane * 4], hxa, hxb);

        const __half* prow = &g_P[(size_t)j * 512 + lane * 4];
        __half2 p0a, p0b, p1a, p1b, p2a, p2b, p3a, p3b;
        ld_h2pair(prow + 0,   p0a, p0b);
        ld_h2pair(prow + 128, p1a, p1b);
        ld_h2pair(prow + 256, p2a, p2b);
        ld_h2pair(prow + 384, p3a, p3b);

        // mask0 (sum): fp32 accumulate
        {
            __half2 m = __hfma2(htanh2(__hadd2(c0a, p0a)), hxa, hxa);
            float2 f = __half22float2(m); s0.x += f.x; s0.y += f.y;
            m = __hfma2(htanh2(__hadd2(c0b, p0b)), hxb, hxb);
            f = __half22float2(m); s0.z += f.x; s0.w += f.y;
        }
        // mask1 (mean): fp32 accumulate
        {
            __half2 m = __hfma2(htanh2(__hadd2(c1a, p1a)), hxa, hxa);
            float2 f = __half22float2(m); s1.x += f.x; s1.y += f.y;
            m = __hfma2(htanh2(__hadd2(c1b, p1b)), hxb, hxb);
            f = __half22float2(m); s1.z += f.x; s1.w += f.y;
        }
        // mask2 (max): half2 accumulate
        {
            s2a = __hmax2(s2a, __hfma2(htanh2(__hadd2(c2a, p2a)), hxa, hxa));
            s2b = __hmax2(s2b, __hfma2(htanh2(__hadd2(c2b, p2b)), hxb, hxb));
        }
        // mask3 (min): half2 accumulate
        {
            s3a = __hmin2(s3a, __hfma2(htanh2(__hadd2(c3a, p3a)), hxa, hxa));
            s3b = __hmin2(s3b, __hfma2(htanh2(__hadd2(c3b, p3b)), hxb, hxb));
        }
    }

    const float inv_deg = 1.0f / (float)DEG;
    float4 h0 = add4(xi, s0);
    float4 h1 = add4(xi, make_float4(s1.x * inv_deg, s1.y * inv_deg,
                                     s1.z * inv_deg, s1.w * inv_deg));
    float2 f2a = __half22float2(s2a), f2b = __half22float2(s2b);
    float2 f3a = __half22float2(s3a), f3b = __half22float2(s3b);
    float4 h2 = add4(xi, make_float4(f2a.x, f2a.y, f2b.x, f2b.y));
    float4 h3 = add4(xi, make_float4(f3a.x, f3a.y, f3b.x, f3b.y));

    __nv_bfloat16* a2 = &g_A2[(size_t)i * 1536];
    bsplit_store(a2, 0   + lane * 4, h0);
    bsplit_store(a2, 128 + lane * 4, h1);
    bsplit_store(a2, 256 + lane * 4, h2);
    bsplit_store(a2, 384 + lane * 4, h3);
}

// ===========================================================================
// Kernel 3: out = relu(A2 @ B2^T + bias)  (M=10000, N=128, K=1536, bf16 HMMA)
// R7 config: tile M=80 x N=64, grid (125,2), 128 threads, 2-stage BK=128.
// ===========================================================================
#define OUT_NKB    12
#define OUT_AST    136
#define OUT_ABYTES (80 * OUT_AST * 2)
#define OUT_BBYTES (64 * OUT_AST * 2)
#define OUT_STAGE  (OUT_ABYTES + OUT_BBYTES)
#define OUT_SMEM   (2 * OUT_STAGE)

__global__ __launch_bounds__(128) void gemm_out_bsplit_kernel(
    const float* __restrict__ bias, float* __restrict__ out)
{
    extern __shared__ char smem[];
    const uint32_t sbase = smem_u32(smem);
    const int tid  = threadIdx.x;
    const int lane = tid & 31;
    const int wid  = tid >> 5;
    const int rowBase   = blockIdx.x * 80;
    const int nTileBase = blockIdx.y * 64;
    const int nbase     = wid * 16;

    float acc[5][2][4];
#pragma unroll
    for (int mt = 0; mt < 5; mt++)
#pragma unroll
        for (int nt = 0; nt < 2; nt++)
#pragma unroll
            for (int e = 0; e < 4; e++) acc[mt][nt][e] = 0.f;

    auto issue = [&](int kb, int s) {
        const uint32_t abase = sbase + s * OUT_STAGE;
        for (int v = tid; v < 1280; v += 128) {
            int r = v >> 4, q = v & 15;
            cp_async16(abase + (r * OUT_AST + q * 8) * 2,
                       &g_A2[(size_t)(rowBase + r) * 1536 + kb * 128 + q * 8]);
        }
        const uint32_t bbase = abase + OUT_ABYTES;
        for (int v = tid; v < 1024; v += 128) {
            int n = v >> 4, q = v & 15;
            cp_async16(bbase + (n * OUT_AST + q * 8) * 2,
                       &g_B2[(size_t)(nTileBase + n) * 1536 + kb * 128 + q * 8]);
        }
        asm volatile("cp.async.commit_group;" ::: "memory");
    };

    issue(0, 0);

#pragma unroll
    for (int kb = 0; kb < OUT_NKB; kb++) {
        if (kb + 1 < OUT_NKB) {
            issue(kb + 1, (kb + 1) & 1);
            asm volatile("cp.async.wait_group 1;" ::: "memory");
        } else {
            asm volatile("cp.async.wait_group 0;" ::: "memory");
        }
        __syncthreads();

        const uint32_t aS = sbase + (kb & 1) * OUT_STAGE;
        const uint32_t bS = aS + OUT_ABYTES;

#pragma unroll
        for (int ks = 0; ks < 8; ks++) {
            const int col = ks * 16;
            uint32_t aF[5][4];
#pragma unroll
            for (int mt = 0; mt < 5; mt++) {
                int row = mt * 16 + (lane & 15);
                ldmatrix_x4(aF[mt], aS + (row * OUT_AST + col + (lane >> 4) * 8) * 2);
            }
            uint32_t bF[2][2];
#pragma unroll
            for (int nt = 0; nt < 2; nt++) {
                int nrow = nbase + nt * 8 + (lane & 7);
                ldmatrix_x2(bF[nt], bS + (nrow * OUT_AST + col + ((lane & 15) >> 3) * 8) * 2);
            }
#pragma unroll
            for (int mt = 0; mt < 5; mt++)
#pragma unroll
                for (int nt = 0; nt < 2; nt++)
                    mma_bf16(acc[mt][nt], aF[mt], bF[nt]);
        }
        __syncthreads();
    }

    // Epilogue: bias + relu
#pragma unroll
    for (int mt = 0; mt < 5; mt++) {
        const int r0 = rowBase + mt * 16 + (lane >> 2);
        const int r1 = r0 + 8;
#pragma unroll
        for (int nt = 0; nt < 2; nt++) {
            const int c = nTileBase + nbase + nt * 8 + (lane & 3) * 2;
            const float b0 = bias[c], b1 = bias[c + 1];
            *(float2*)&out[(size_t)r0 * 128 + c] = make_float2(
                fmaxf(acc[mt][nt][0] + b0, 0.f), fmaxf(acc[mt][nt][1] + b1, 0.f));
            *(float2*)&out[(size_t)r1 * 128 + c] = make_float2(
                fmaxf(acc[mt][nt][2] + b0, 0.f), fmaxf(acc[mt][nt][3] + b1, 0.f));
        }
    }
}

// ===========================================================================
extern "C" void kernel_launch(void* const* d_in, const int* in_sizes, int n_in,
                              void* d_out, int out_size)
{
    const float* x     = (const float*)d_in[0];
    const int*   nbr   = (const int*)  d_in[1];
    const float* Wsum  = (const float*)d_in[2];
    const float* Wmean = (const float*)d_in[3];
    const float* Wmax  = (const float*)d_in[4];
    const float* Wmin  = (const float*)d_in[5];
    const float* W     = (const float*)d_in[6];
    const float* bias  = (const float*)d_in[7];
    float* out = (float*)d_out;

    const int CP_SMEM = 2 * 128 * CP_STRIDE * 2;  // 69,632 B
    cudaFuncSetAttribute(gemm_cp_mma_kernel,
                         cudaFuncAttributeMaxDynamicSharedMemorySize, CP_SMEM);
    cudaFuncSetAttribute(gemm_out_bsplit_kernel,
                         cudaFuncAttributeMaxDynamicSharedMemorySize, OUT_SMEM);

    // 0) conversions + weight splits
    prep_kernel<<<296, 256>>>(x, Wsum, Wmean, Wmax, Wmin, W);

    // 1) CP = 0.5 * Xb @ Wb^T (10000 x 1024), bf16 HMMA -> fp16 C/P
    {
        dim3 grid(1024 / 128, (NN + 127) / 128);
        gemm_cp_mma_kernel<<<grid, 256, CP_SMEM>>>();
    }

    // 2) per-node aggregation (half2 pipeline) -> A2 (split H)
    {
        dim3 grid((NN + 3) / 4);
        agg_kernel<<<grid, 128>>>(x, nbr);
    }

    // 3) out = relu(A2 @ B2^T + bias), bf16 HMMA split-precision (R7 config)
    {
        dim3 grid(125, 2);
        gemm_out_bsplit_kernel<<<grid, 128, OUT_SMEM>>>(bias, out);
    }
}